// round 1
// baseline (speedup 1.0000x reference)
#include <cuda_runtime.h>
#include <cuda_bf16.h>
#include <math.h>

#define B_ 4
#define N_ 2048
#define C_ 1024
#define H_ 16
#define D_ 64
#define FF_ 4096
#define M_ (B_ * N_)   // 8192 rows

// ---------------- scratch (static device globals; no runtime allocation) ----
__device__ float g_h  [M_ * C_];        // LN output (reused for ln1 and ln2)
__device__ float g_qkv[M_ * 3 * C_];    // qkv projections
__device__ float g_o  [M_ * C_];        // attention output (B,N,C)
__device__ float g_x1 [M_ * C_];        // residual after attention
__device__ float g_u  [M_ * FF_];       // h@w1^T  (later: silu(u)*g)
__device__ float g_g  [M_ * FF_];       // h@w3^T

// ---------------- LayerNorm: one block per row, 256 threads ----------------
__global__ void __launch_bounds__(256) layernorm_k(
    const float* __restrict__ x, const float* __restrict__ gam,
    const float* __restrict__ bet, float* __restrict__ out)
{
    int row = blockIdx.x;
    const float* xr = x + (size_t)row * C_;
    float* orow = out + (size_t)row * C_;
    int t = threadIdx.x;

    float4 v = *(const float4*)(xr + t * 4);
    float s1 = v.x + v.y + v.z + v.w;
    float s2 = v.x*v.x + v.y*v.y + v.z*v.z + v.w*v.w;

    #pragma unroll
    for (int o = 16; o; o >>= 1) {
        s1 += __shfl_xor_sync(0xffffffffu, s1, o);
        s2 += __shfl_xor_sync(0xffffffffu, s2, o);
    }
    __shared__ float r1[8], r2[8];
    __shared__ float mu_s, rs_s;
    if ((t & 31) == 0) { r1[t >> 5] = s1; r2[t >> 5] = s2; }
    __syncthreads();
    if (t == 0) {
        float a = 0.f, b = 0.f;
        #pragma unroll
        for (int i = 0; i < 8; i++) { a += r1[i]; b += r2[i]; }
        float mu = a * (1.f / C_);
        float var = b * (1.f / C_) - mu * mu;
        mu_s = mu;
        rs_s = rsqrtf(var + 1e-6f);
    }
    __syncthreads();
    float mu = mu_s, rs = rs_s;
    float4 gv = *(const float4*)(gam + t * 4);
    float4 bv = *(const float4*)(bet + t * 4);
    float4 ov;
    ov.x = (v.x - mu) * rs * gv.x + bv.x;
    ov.y = (v.y - mu) * rs * gv.y + bv.y;
    ov.z = (v.z - mu) * rs * gv.z + bv.z;
    ov.w = (v.w - mu) * rs * gv.w + bv.w;
    *(float4*)(orow + t * 4) = ov;
}

// ---------------- SGEMM: C = A(MxK) * B(NxK)^T (+bias)(+res) ---------------
// 128x128 tile, BK=8, 256 threads, 8x8 per-thread microtile.
// All shapes used divide tiles exactly (M=8192; N in {1024,3072,4096}; K in {1024,4096}).
#define BM 128
#define BN 128
#define BK 8

template<bool BIAS, bool RES>
__global__ void __launch_bounds__(256) sgemm_nt(
    const float* __restrict__ A, const float* __restrict__ Bm,
    const float* __restrict__ bias, const float* __restrict__ res,
    float* __restrict__ Cc, int M, int Nn, int K)
{
    __shared__ float As[BK][BM];
    __shared__ float Bs[BK][BN];
    int tid = threadIdx.x;
    int m0 = blockIdx.y * BM;
    int n0 = blockIdx.x * BN;

    int lr = tid >> 1;           // 0..127
    int lc = (tid & 1) * 4;      // 0 or 4
    const float* Ap = A  + (size_t)(m0 + lr) * K + lc;
    const float* Bp = Bm + (size_t)(n0 + lr) * K + lc;

    int ty = tid >> 4;           // 0..15
    int tx = tid & 15;           // 0..15

    float acc[8][8] = {};

    for (int k0 = 0; k0 < K; k0 += BK) {
        float4 av = *(const float4*)(Ap + k0);
        float4 bv = *(const float4*)(Bp + k0);
        As[lc + 0][lr] = av.x; As[lc + 1][lr] = av.y;
        As[lc + 2][lr] = av.z; As[lc + 3][lr] = av.w;
        Bs[lc + 0][lr] = bv.x; Bs[lc + 1][lr] = bv.y;
        Bs[lc + 2][lr] = bv.z; Bs[lc + 3][lr] = bv.w;
        __syncthreads();
        #pragma unroll
        for (int k = 0; k < BK; k++) {
            float a[8], b[8];
            #pragma unroll
            for (int i = 0; i < 8; i++) a[i] = As[k][ty * 8 + i];
            #pragma unroll
            for (int j = 0; j < 8; j++) b[j] = Bs[k][tx * 8 + j];
            #pragma unroll
            for (int i = 0; i < 8; i++)
                #pragma unroll
                for (int j = 0; j < 8; j++)
                    acc[i][j] = fmaf(a[i], b[j], acc[i][j]);
        }
        __syncthreads();
    }

    #pragma unroll
    for (int i = 0; i < 8; i++) {
        int m = m0 + ty * 8 + i;
        #pragma unroll
        for (int j = 0; j < 8; j += 4) {
            int n = n0 + tx * 8 + j;
            float4 o;
            o.x = acc[i][j];     o.y = acc[i][j + 1];
            o.z = acc[i][j + 2]; o.w = acc[i][j + 3];
            if (BIAS) {
                o.x += bias[n];     o.y += bias[n + 1];
                o.z += bias[n + 2]; o.w += bias[n + 3];
            }
            if (RES) {
                float4 r = *(const float4*)(res + (size_t)m * Nn + n);
                o.x += r.x; o.y += r.y; o.z += r.z; o.w += r.w;
            }
            *(float4*)(Cc + (size_t)m * Nn + n) = o;
        }
    }
}

// ---------------- causal flash attention, fp32 ------------------------------
// grid (N/64, B*H); 64 threads; thread t owns query row (qtile*64 + t).
// qkv layout [B, N, 3C]: q at col h*D+d, k at C + h*D+d, v at 2C + h*D+d.
#define BR 64
#define BC 64

__global__ void __launch_bounds__(64) flash_attn_k(
    const float* __restrict__ qkv, float* __restrict__ O)
{
    int qt = blockIdx.x;
    int bh = blockIdx.y;
    int b = bh / H_, h = bh % H_;
    int t = threadIdx.x;
    int qi = qt * BR + t;

    const float* base = qkv + (size_t)b * N_ * (3 * C_);
    const float* qp = base + (size_t)qi * (3 * C_) + h * D_;

    float q[D_];
    #pragma unroll
    for (int d = 0; d < D_; d++) q[d] = qp[d] * 0.125f;  // D^-0.5

    float m = -INFINITY, l = 0.f;
    float acc[D_] = {};

    __shared__ float Ks[BC][D_];
    __shared__ float Vs[BC][D_];
    __shared__ float Ss[BR][BC + 1];   // +1 pad: conflict-free row writes

    int nkt = qt + 1;   // causal: key tiles 0..qt
    for (int kt = 0; kt < nkt; kt++) {
        __syncthreads();
        // thread t loads column t of K and V tiles (coalesced across threads)
        for (int j = 0; j < BC; j++) {
            const float* kp = base + (size_t)(kt * BC + j) * (3 * C_) + C_ + h * D_;
            Ks[j][t] = kp[t];
            Vs[j][t] = kp[C_ + t];
        }
        __syncthreads();

        int jmax = (kt == qt) ? (t + 1) : BC;  // diagonal tile: keys j <= t valid
        float mt = -INFINITY;
        for (int j = 0; j < jmax; j++) {
            float s = 0.f;
            #pragma unroll
            for (int d = 0; d < D_; d++) s = fmaf(q[d], Ks[j][d], s);
            Ss[t][j] = s;
            mt = fmaxf(mt, s);
        }
        float nm = fmaxf(m, mt);
        float corr = __expf(m - nm);
        l *= corr;
        #pragma unroll
        for (int d = 0; d < D_; d++) acc[d] *= corr;
        for (int j = 0; j < jmax; j++) {
            float p = __expf(Ss[t][j] - nm);
            l += p;
            #pragma unroll
            for (int d = 0; d < D_; d++) acc[d] = fmaf(p, Vs[j][d], acc[d]);
        }
        m = nm;
    }

    float inv = 1.f / l;
    float* op = O + (size_t)b * N_ * C_ + (size_t)qi * C_ + h * D_;
    #pragma unroll
    for (int d = 0; d < D_; d++) op[d] = acc[d] * inv;
}

// ---------------- silu(u) * g -> out ---------------------------------------
__global__ void __launch_bounds__(256) silu_mul_k(
    const float* __restrict__ u, const float* __restrict__ g,
    float* __restrict__ out, int n)
{
    int i = blockIdx.x * 256 + threadIdx.x;
    if (i < n) {
        float x = u[i];
        float s = x / (1.f + __expf(-x));
        out[i] = s * g[i];
    }
}

// ---------------- launcher --------------------------------------------------
extern "C" void kernel_launch(void* const* d_in, const int* in_sizes, int n_in,
                              void* d_out, int out_size)
{
    const float* x      = (const float*)d_in[0];
    // d_in[1] = mask (causal tril) — causality is applied analytically, input ignored
    const float* qkv_w  = (const float*)d_in[2];
    const float* qkv_b  = (const float*)d_in[3];
    const float* proj_w = (const float*)d_in[4];
    const float* proj_b = (const float*)d_in[5];
    const float* ln1_g  = (const float*)d_in[6];
    const float* ln1_b  = (const float*)d_in[7];
    const float* ln2_g  = (const float*)d_in[8];
    const float* ln2_b  = (const float*)d_in[9];
    const float* w1     = (const float*)d_in[10];
    const float* w2     = (const float*)d_in[11];
    const float* w3     = (const float*)d_in[12];
    float* out = (float*)d_out;

    float *h, *qkv, *o, *x1, *u, *g;
    cudaGetSymbolAddress((void**)&h,   g_h);
    cudaGetSymbolAddress((void**)&qkv, g_qkv);
    cudaGetSymbolAddress((void**)&o,   g_o);
    cudaGetSymbolAddress((void**)&x1,  g_x1);
    cudaGetSymbolAddress((void**)&u,   g_u);
    cudaGetSymbolAddress((void**)&g,   g_g);

    // 1) h = LN1(x)
    layernorm_k<<<M_, 256>>>(x, ln1_g, ln1_b, h);
    // 2) qkv = h @ qkv_w^T + qkv_b          [8192, 3072]
    sgemm_nt<true, false><<<dim3(3 * C_ / BN, M_ / BM), 256>>>(
        h, qkv_w, qkv_b, nullptr, qkv, M_, 3 * C_, C_);
    // 3) o = causal_attention(qkv)          [B,N,C]
    flash_attn_k<<<dim3(N_ / BR, B_ * H_), 64>>>(qkv, o);
    // 4) x1 = x + o @ proj_w^T + proj_b
    sgemm_nt<true, true><<<dim3(C_ / BN, M_ / BM), 256>>>(
        o, proj_w, proj_b, x, x1, M_, C_, C_);
    // 5) h = LN2(x1)
    layernorm_k<<<M_, 256>>>(x1, ln2_g, ln2_b, h);
    // 6) u = h @ w1^T ; g = h @ w3^T        [8192, 4096]
    sgemm_nt<false, false><<<dim3(FF_ / BN, M_ / BM), 256>>>(
        h, w1, nullptr, nullptr, u, M_, FF_, C_);
    sgemm_nt<false, false><<<dim3(FF_ / BN, M_ / BM), 256>>>(
        h, w3, nullptr, nullptr, g, M_, FF_, C_);
    // 7) u = silu(u) * g
    silu_mul_k<<<(M_ * FF_) / 256, 256>>>(u, g, u, M_ * FF_);
    // 8) out = x1 + u @ w2^T
    sgemm_nt<false, true><<<dim3(C_ / BN, M_ / BM), 256>>>(
        u, w2, nullptr, x1, out, M_, C_, FF_);
}

// round 3
// speedup vs baseline: 2.1800x; 2.1800x over previous
#include <cuda_runtime.h>
#include <cuda_bf16.h>
#include <math.h>
#include <stdint.h>

#define B_ 4
#define N_ 2048
#define C_ 1024
#define H_ 16
#define D_ 64
#define FF_ 4096
#define M_ (B_ * N_)   // 8192 rows

// ---------------- scratch ----------------------------------------------------
__device__ float g_h  [M_ * C_];
__device__ float g_qkv[M_ * 3 * C_];
__device__ float g_o  [M_ * C_];
__device__ float g_x1 [M_ * C_];
__device__ float g_u  [M_ * FF_];
__device__ float g_g  [M_ * FF_];
// tf32-rounded weights
__device__ float g_wq [3 * C_ * C_];
__device__ float g_wp [C_ * C_];
__device__ float g_w1 [FF_ * C_];
__device__ float g_w2 [C_ * FF_];
__device__ float g_w3 [FF_ * C_];

// ---------------- helpers ----------------------------------------------------
__device__ __forceinline__ uint32_t smem_u32(const void* p) {
    uint32_t a;
    asm("{ .reg .u64 t; cvta.to.shared.u64 t, %1; cvt.u32.u64 %0, t; }" : "=r"(a) : "l"(p));
    return a;
}
__device__ __forceinline__ float tf32_rna(float x) {
    uint32_t u;
    asm("cvt.rna.tf32.f32 %0, %1;" : "=r"(u) : "f"(x));
    return __uint_as_float(u);
}
#define CP_ASYNC16(dst, src) \
    asm volatile("cp.async.cg.shared.global [%0], [%1], 16;" :: "r"(dst), "l"(src))
#define CP_COMMIT() asm volatile("cp.async.commit_group;" ::: "memory")
#define CP_WAIT(n)  asm volatile("cp.async.wait_group %0;" :: "n"(n) : "memory")

__device__ __forceinline__ void mma_tf32(float* c, const uint32_t* a, const uint32_t* b) {
    asm volatile(
        "mma.sync.aligned.m16n8k8.row.col.f32.tf32.tf32.f32 "
        "{%0,%1,%2,%3}, {%4,%5,%6,%7}, {%8,%9}, {%0,%1,%2,%3};"
        : "+f"(c[0]), "+f"(c[1]), "+f"(c[2]), "+f"(c[3])
        : "r"(a[0]), "r"(a[1]), "r"(a[2]), "r"(a[3]), "r"(b[0]), "r"(b[1]));
}

// ---------------- tf32 rounding prepass --------------------------------------
__global__ void __launch_bounds__(256) cvt_tf32_k(const float* __restrict__ in,
                                                  float* __restrict__ out, int n4)
{
    int i = blockIdx.x * 256 + threadIdx.x;
    if (i < n4) {
        float4 v = ((const float4*)in)[i];
        v.x = tf32_rna(v.x); v.y = tf32_rna(v.y);
        v.z = tf32_rna(v.z); v.w = tf32_rna(v.w);
        ((float4*)out)[i] = v;
    }
}

// ---------------- LayerNorm (output pre-rounded to tf32) ---------------------
__global__ void __launch_bounds__(256) layernorm_k(
    const float* __restrict__ x, const float* __restrict__ gam,
    const float* __restrict__ bet, float* __restrict__ out)
{
    int row = blockIdx.x;
    const float* xr = x + (size_t)row * C_;
    float* orow = out + (size_t)row * C_;
    int t = threadIdx.x;

    float4 v = *(const float4*)(xr + t * 4);
    float s1 = v.x + v.y + v.z + v.w;
    float s2 = v.x*v.x + v.y*v.y + v.z*v.z + v.w*v.w;
    #pragma unroll
    for (int o = 16; o; o >>= 1) {
        s1 += __shfl_xor_sync(0xffffffffu, s1, o);
        s2 += __shfl_xor_sync(0xffffffffu, s2, o);
    }
    __shared__ float r1[8], r2[8];
    __shared__ float mu_s, rs_s;
    if ((t & 31) == 0) { r1[t >> 5] = s1; r2[t >> 5] = s2; }
    __syncthreads();
    if (t == 0) {
        float a = 0.f, b = 0.f;
        #pragma unroll
        for (int i = 0; i < 8; i++) { a += r1[i]; b += r2[i]; }
        float mu = a * (1.f / C_);
        float var = b * (1.f / C_) - mu * mu;
        mu_s = mu; rs_s = rsqrtf(var + 1e-6f);
    }
    __syncthreads();
    float mu = mu_s, rs = rs_s;
    float4 gv = *(const float4*)(gam + t * 4);
    float4 bv = *(const float4*)(bet + t * 4);
    float4 ov;
    ov.x = tf32_rna((v.x - mu) * rs * gv.x + bv.x);
    ov.y = tf32_rna((v.y - mu) * rs * gv.y + bv.y);
    ov.z = tf32_rna((v.z - mu) * rs * gv.z + bv.z);
    ov.w = tf32_rna((v.w - mu) * rs * gv.w + bv.w);
    *(float4*)(orow + t * 4) = ov;
}

// ---------------- tf32 mma.sync GEMM: C = A(MxK)*B(NxK)^T (+bias)(+res) ------
// 128x128 tile, BK=16, 3-stage cp.async, 256 threads, 8 warps (2x4), 64x32/warp.
#define BKG 16
#define PADK 20                       // row stride in floats (conflict-free)
#define TILE_FLOATS (128 * PADK)      // 2560
#define STAGE_FLOATS (2 * TILE_FLOATS)
#define GSMEM_BYTES (3 * STAGE_FLOATS * 4)   // 61440

template<bool BIAS, bool RES>
__global__ void __launch_bounds__(256, 2) mma_gemm(
    const float* __restrict__ A, const float* __restrict__ Bm,
    const float* __restrict__ bias, const float* __restrict__ res,
    float* __restrict__ Cc, int M, int Nn, int K)
{
    extern __shared__ float sm[];
    uint32_t sb = smem_u32(sm);
    const int tid = threadIdx.x;
    const int m0 = blockIdx.y * 128;
    const int n0 = blockIdx.x * 128;
    const int warp = tid >> 5, lane = tid & 31;
    const int m0w = (warp >> 2) * 64;
    const int n0w = (warp & 3) * 32;
    const int gr = lane >> 2, q = lane & 3;

    const int lrow = tid >> 1;
    const int lk = (tid & 1) * 8;
    const float* Ap = A  + (size_t)(m0 + lrow) * K + lk;
    const float* Bp = Bm + (size_t)(n0 + lrow) * K + lk;
    const uint32_t woA = (uint32_t)(lrow * PADK + lk) * 4;
    const uint32_t woB = woA + TILE_FLOATS * 4;

    float acc[4][4][4];
    #pragma unroll
    for (int i = 0; i < 4; i++)
        #pragma unroll
        for (int j = 0; j < 4; j++)
            #pragma unroll
            for (int c = 0; c < 4; c++) acc[i][j][c] = 0.f;

    const int NS = K / BKG;

    #pragma unroll
    for (int s = 0; s < 2; s++) {
        uint32_t st = sb + (uint32_t)s * STAGE_FLOATS * 4;
        CP_ASYNC16(st + woA,      Ap + s * BKG);
        CP_ASYNC16(st + woA + 16, Ap + s * BKG + 4);
        CP_ASYNC16(st + woB,      Bp + s * BKG);
        CP_ASYNC16(st + woB + 16, Bp + s * BKG + 4);
        CP_COMMIT();
    }

    for (int s = 0; s < NS; s++) {
        if (s == NS - 1) CP_WAIT(0); else CP_WAIT(1);
        __syncthreads();

        int ns = s + 2;
        if (ns < NS) {
            uint32_t st = sb + (uint32_t)(ns % 3) * STAGE_FLOATS * 4;
            CP_ASYNC16(st + woA,      Ap + ns * BKG);
            CP_ASYNC16(st + woA + 16, Ap + ns * BKG + 4);
            CP_ASYNC16(st + woB,      Bp + ns * BKG);
            CP_ASYNC16(st + woB + 16, Bp + ns * BKG + 4);
            CP_COMMIT();
        }

        const float* sA = sm + (s % 3) * STAGE_FLOATS;
        const float* sB = sA + TILE_FLOATS;

        #pragma unroll
        for (int kk = 0; kk < BKG; kk += 8) {
            uint32_t a[4][4], b[4][2];
            #pragma unroll
            for (int mi = 0; mi < 4; mi++) {
                int r = m0w + mi * 16 + gr;
                a[mi][0] = __float_as_uint(sA[r * PADK + kk + q]);
                a[mi][1] = __float_as_uint(sA[(r + 8) * PADK + kk + q]);
                a[mi][2] = __float_as_uint(sA[r * PADK + kk + q + 4]);
                a[mi][3] = __float_as_uint(sA[(r + 8) * PADK + kk + q + 4]);
            }
            #pragma unroll
            for (int ni = 0; ni < 4; ni++) {
                int c = n0w + ni * 8 + gr;
                b[ni][0] = __float_as_uint(sB[c * PADK + kk + q]);
                b[ni][1] = __float_as_uint(sB[c * PADK + kk + q + 4]);
            }
            #pragma unroll
            for (int mi = 0; mi < 4; mi++)
                #pragma unroll
                for (int ni = 0; ni < 4; ni++)
                    mma_tf32(acc[mi][ni], a[mi], b[ni]);
        }
        __syncthreads();
    }

    // epilogue
    #pragma unroll
    for (int mi = 0; mi < 4; mi++) {
        int m = m0 + m0w + mi * 16 + gr;
        #pragma unroll
        for (int ni = 0; ni < 4; ni++) {
            int n = n0 + n0w + ni * 8 + 2 * q;
            float2 v0 = make_float2(acc[mi][ni][0], acc[mi][ni][1]);
            float2 v1 = make_float2(acc[mi][ni][2], acc[mi][ni][3]);
            if (BIAS) {
                float2 bv = *(const float2*)(bias + n);
                v0.x += bv.x; v0.y += bv.y;
                v1.x += bv.x; v1.y += bv.y;
            }
            if (RES) {
                float2 r0 = *(const float2*)(res + (size_t)m * Nn + n);
                float2 r1 = *(const float2*)(res + (size_t)(m + 8) * Nn + n);
                v0.x += r0.x; v0.y += r0.y;
                v1.x += r1.x; v1.y += r1.y;
            }
            *(float2*)(Cc + (size_t)m * Nn + n) = v0;
            *(float2*)(Cc + (size_t)(m + 8) * Nn + n) = v1;
        }
    }
}

// ---------------- causal flash attention (fp32, float4 LDS) ------------------
#define BR 64
#define BC 64

__global__ void __launch_bounds__(64) flash_attn_k(
    const float* __restrict__ qkv, float* __restrict__ O)
{
    int qt = blockIdx.x;
    int bh = blockIdx.y;
    int b = bh / H_, h = bh % H_;
    int t = threadIdx.x;
    int qi = qt * BR + t;

    const float* base = qkv + (size_t)b * N_ * (3 * C_);
    const float* qp = base + (size_t)qi * (3 * C_) + h * D_;

    float4 q4[16];
    #pragma unroll
    for (int d = 0; d < 16; d++) {
        float4 v = *(const float4*)(qp + d * 4);
        v.x *= 0.125f; v.y *= 0.125f; v.z *= 0.125f; v.w *= 0.125f;
        q4[d] = v;
    }

    float m = -INFINITY, l = 0.f;
    float4 acc[16];
    #pragma unroll
    for (int d = 0; d < 16; d++) acc[d] = make_float4(0.f, 0.f, 0.f, 0.f);

    __shared__ float4 Ks[BC][16];
    __shared__ float4 Vs[BC][16];
    __shared__ float  Ss[BC][BR];   // [j][t] — conflict-free; total smem = 48KB

    int nkt = qt + 1;
    for (int kt = 0; kt < nkt; kt++) {
        __syncthreads();
        for (int j = 0; j < BC; j++) {
            const float* kp = base + (size_t)(kt * BC + j) * (3 * C_) + C_ + h * D_;
            ((float*)&Ks[j][0])[t] = kp[t];
            ((float*)&Vs[j][0])[t] = kp[C_ + t];
        }
        __syncthreads();

        int jmax = (kt == qt) ? (t + 1) : BC;
        float mt = -INFINITY;
        for (int j = 0; j < jmax; j++) {
            float s = 0.f;
            #pragma unroll
            for (int d = 0; d < 16; d++) {
                float4 kv = Ks[j][d];
                s = fmaf(q4[d].x, kv.x, s);
                s = fmaf(q4[d].y, kv.y, s);
                s = fmaf(q4[d].z, kv.z, s);
                s = fmaf(q4[d].w, kv.w, s);
            }
            Ss[j][t] = s;
            mt = fmaxf(mt, s);
        }
        float nm = fmaxf(m, mt);
        float corr = __expf(m - nm);
        l *= corr;
        #pragma unroll
        for (int d = 0; d < 16; d++) {
            acc[d].x *= corr; acc[d].y *= corr; acc[d].z *= corr; acc[d].w *= corr;
        }
        for (int j = 0; j < jmax; j++) {
            float p = __expf(Ss[j][t] - nm);
            l += p;
            #pragma unroll
            for (int d = 0; d < 16; d++) {
                float4 vv = Vs[j][d];
                acc[d].x = fmaf(p, vv.x, acc[d].x);
                acc[d].y = fmaf(p, vv.y, acc[d].y);
                acc[d].z = fmaf(p, vv.z, acc[d].z);
                acc[d].w = fmaf(p, vv.w, acc[d].w);
            }
        }
        m = nm;
    }

    float inv = 1.f / l;
    float* op = O + (size_t)b * N_ * C_ + (size_t)qi * C_ + h * D_;
    #pragma unroll
    for (int d = 0; d < 16; d++) {
        float4 o;
        o.x = tf32_rna(acc[d].x * inv); o.y = tf32_rna(acc[d].y * inv);
        o.z = tf32_rna(acc[d].z * inv); o.w = tf32_rna(acc[d].w * inv);
        *(float4*)(op + d * 4) = o;
    }
}

// ---------------- silu(u) * g (output pre-rounded to tf32) -------------------
__global__ void __launch_bounds__(256) silu_mul_k(
    const float* __restrict__ u, const float* __restrict__ g,
    float* __restrict__ out, int n4)
{
    int i = blockIdx.x * 256 + threadIdx.x;
    if (i < n4) {
        float4 a = ((const float4*)u)[i];
        float4 b = ((const float4*)g)[i];
        float4 o;
        o.x = tf32_rna(a.x / (1.f + __expf(-a.x)) * b.x);
        o.y = tf32_rna(a.y / (1.f + __expf(-a.y)) * b.y);
        o.z = tf32_rna(a.z / (1.f + __expf(-a.z)) * b.z);
        o.w = tf32_rna(a.w / (1.f + __expf(-a.w)) * b.w);
        ((float4*)out)[i] = o;
    }
}

// ---------------- launcher ---------------------------------------------------
extern "C" void kernel_launch(void* const* d_in, const int* in_sizes, int n_in,
                              void* d_out, int out_size)
{
    const float* x      = (const float*)d_in[0];
    const float* qkv_w  = (const float*)d_in[2];
    const float* qkv_b  = (const float*)d_in[3];
    const float* proj_w = (const float*)d_in[4];
    const float* proj_b = (const float*)d_in[5];
    const float* ln1_g  = (const float*)d_in[6];
    const float* ln1_b  = (const float*)d_in[7];
    const float* ln2_g  = (const float*)d_in[8];
    const float* ln2_b  = (const float*)d_in[9];
    const float* w1     = (const float*)d_in[10];
    const float* w2     = (const float*)d_in[11];
    const float* w3     = (const float*)d_in[12];
    float* out = (float*)d_out;

    float *h, *qkv, *o, *x1, *u, *g, *wq, *wp, *tw1, *tw2, *tw3;
    cudaGetSymbolAddress((void**)&h,   g_h);
    cudaGetSymbolAddress((void**)&qkv, g_qkv);
    cudaGetSymbolAddress((void**)&o,   g_o);
    cudaGetSymbolAddress((void**)&x1,  g_x1);
    cudaGetSymbolAddress((void**)&u,   g_u);
    cudaGetSymbolAddress((void**)&g,   g_g);
    cudaGetSymbolAddress((void**)&wq,  g_wq);
    cudaGetSymbolAddress((void**)&wp,  g_wp);
    cudaGetSymbolAddress((void**)&tw1, g_w1);
    cudaGetSymbolAddress((void**)&tw2, g_w2);
    cudaGetSymbolAddress((void**)&tw3, g_w3);

    cudaFuncSetAttribute(mma_gemm<true,  false>, cudaFuncAttributeMaxDynamicSharedMemorySize, GSMEM_BYTES);
    cudaFuncSetAttribute(mma_gemm<true,  true >, cudaFuncAttributeMaxDynamicSharedMemorySize, GSMEM_BYTES);
    cudaFuncSetAttribute(mma_gemm<false, false>, cudaFuncAttributeMaxDynamicSharedMemorySize, GSMEM_BYTES);
    cudaFuncSetAttribute(mma_gemm<false, true >, cudaFuncAttributeMaxDynamicSharedMemorySize, GSMEM_BYTES);

    // 0) round weights to tf32 (rna)
    cvt_tf32_k<<<(3*C_*C_/4 + 255)/256, 256>>>(qkv_w,  wq,  3*C_*C_/4);
    cvt_tf32_k<<<(C_*C_/4   + 255)/256, 256>>>(proj_w, wp,  C_*C_/4);
    cvt_tf32_k<<<(FF_*C_/4  + 255)/256, 256>>>(w1,     tw1, FF_*C_/4);
    cvt_tf32_k<<<(C_*FF_/4  + 255)/256, 256>>>(w2,     tw2, C_*FF_/4);
    cvt_tf32_k<<<(FF_*C_/4  + 255)/256, 256>>>(w3,     tw3, FF_*C_/4);

    // 1) h = LN1(x)
    layernorm_k<<<M_, 256>>>(x, ln1_g, ln1_b, h);
    // 2) qkv = h @ qkv_w^T + qkv_b
    mma_gemm<true, false><<<dim3(3*C_/128, M_/128), 256, GSMEM_BYTES>>>(
        h, wq, qkv_b, nullptr, qkv, M_, 3*C_, C_);
    // 3) o = causal_attention(qkv)
    flash_attn_k<<<dim3(N_/BR, B_*H_), 64>>>(qkv, o);
    // 4) x1 = x + o @ proj_w^T + proj_b
    mma_gemm<true, true><<<dim3(C_/128, M_/128), 256, GSMEM_BYTES>>>(
        o, wp, proj_b, x, x1, M_, C_, C_);
    // 5) h = LN2(x1)
    layernorm_k<<<M_, 256>>>(x1, ln2_g, ln2_b, h);
    // 6) u = h @ w1^T ; g = h @ w3^T
    mma_gemm<false, false><<<dim3(FF_/128, M_/128), 256, GSMEM_BYTES>>>(
        h, tw1, nullptr, nullptr, u, M_, FF_, C_);
    mma_gemm<false, false><<<dim3(FF_/128, M_/128), 256, GSMEM_BYTES>>>(
        h, tw3, nullptr, nullptr, g, M_, FF_, C_);
    // 7) u = silu(u) * g
    silu_mul_k<<<(M_*FF_/4)/256, 256>>>(u, g, u, M_*FF_/4);
    // 8) out = x1 + u @ w2^T
    mma_gemm<false, true><<<dim3(C_/128, M_/128), 256, GSMEM_BYTES>>>(
        u, tw2, nullptr, x1, out, M_, C_, FF_);
}

// round 6
// speedup vs baseline: 3.0643x; 1.4056x over previous
#include <cuda_runtime.h>
#include <cuda_fp16.h>
#include <math.h>
#include <stdint.h>

#define B_ 4
#define N_ 2048
#define C_ 1024
#define H_ 16
#define D_ 64
#define FF_ 4096
#define M_ (B_ * N_)   // 8192 rows

// ---------------- scratch ----------------------------------------------------
__device__ float  g_qkv[M_ * 3 * C_];
__device__ float  g_x1 [M_ * C_];
__device__ float  g_u  [M_ * FF_];
__device__ float  g_g  [M_ * FF_];
__device__ __half g_hh [M_ * C_];      // LN output (half)
__device__ __half g_oh [M_ * C_];      // attention output (half)
__device__ __half g_uh [M_ * FF_];     // silu(u)*g (half)
// fp16 weights
__device__ __half g_wqh[3 * C_ * C_];
__device__ __half g_wph[C_ * C_];
__device__ __half g_w1h[FF_ * C_];
__device__ __half g_w2h[C_ * FF_];
__device__ __half g_w3h[FF_ * C_];

// ---------------- helpers ----------------------------------------------------
__device__ __forceinline__ uint32_t smem_u32(const void* p) {
    uint32_t a;
    asm("{ .reg .u64 t; cvta.to.shared.u64 t, %1; cvt.u32.u64 %0, t; }" : "=r"(a) : "l"(p));
    return a;
}
#define CP_ASYNC16(dst, src) \
    asm volatile("cp.async.cg.shared.global [%0], [%1], 16;" :: "r"(dst), "l"(src))
#define CP_COMMIT() asm volatile("cp.async.commit_group;" ::: "memory")
#define CP_WAIT(n)  asm volatile("cp.async.wait_group %0;" :: "n"(n) : "memory")

#define LDM_X4(r0, r1, r2, r3, addr) \
    asm volatile("ldmatrix.sync.aligned.m8n8.x4.shared.b16 {%0,%1,%2,%3}, [%4];" \
                 : "=r"(r0), "=r"(r1), "=r"(r2), "=r"(r3) : "r"(addr))

__device__ __forceinline__ void mma_f16(float* c, const uint32_t* a,
                                        uint32_t b0, uint32_t b1) {
    asm volatile(
        "mma.sync.aligned.m16n8k16.row.col.f32.f16.f16.f32 "
        "{%0,%1,%2,%3}, {%4,%5,%6,%7}, {%8,%9}, {%0,%1,%2,%3};"
        : "+f"(c[0]), "+f"(c[1]), "+f"(c[2]), "+f"(c[3])
        : "r"(a[0]), "r"(a[1]), "r"(a[2]), "r"(a[3]), "r"(b0), "r"(b1));
}

// ---------------- fp32 -> fp16 prepass ---------------------------------------
__global__ void __launch_bounds__(256) cvt_half_k(const float* __restrict__ in,
                                                  __half* __restrict__ out, int n4)
{
    int i = blockIdx.x * 256 + threadIdx.x;
    if (i < n4) {
        float4 v = ((const float4*)in)[i];
        __half2* o = (__half2*)out + i * 2;
        o[0] = __floats2half2_rn(v.x, v.y);
        o[1] = __floats2half2_rn(v.z, v.w);
    }
}

// ---------------- LayerNorm (half output) ------------------------------------
__global__ void __launch_bounds__(256) layernorm_k(
    const float* __restrict__ x, const float* __restrict__ gam,
    const float* __restrict__ bet, __half* __restrict__ out)
{
    int row = blockIdx.x;
    const float* xr = x + (size_t)row * C_;
    __half2* orow = (__half2*)(out + (size_t)row * C_);
    int t = threadIdx.x;

    float4 v = *(const float4*)(xr + t * 4);
    float s1 = v.x + v.y + v.z + v.w;
    float s2 = v.x*v.x + v.y*v.y + v.z*v.z + v.w*v.w;
    #pragma unroll
    for (int o = 16; o; o >>= 1) {
        s1 += __shfl_xor_sync(0xffffffffu, s1, o);
        s2 += __shfl_xor_sync(0xffffffffu, s2, o);
    }
    __shared__ float r1[8], r2[8];
    __shared__ float mu_s, rs_s;
    if ((t & 31) == 0) { r1[t >> 5] = s1; r2[t >> 5] = s2; }
    __syncthreads();
    if (t == 0) {
        float a = 0.f, b = 0.f;
        #pragma unroll
        for (int i = 0; i < 8; i++) { a += r1[i]; b += r2[i]; }
        float mu = a * (1.f / C_);
        float var = b * (1.f / C_) - mu * mu;
        mu_s = mu; rs_s = rsqrtf(var + 1e-6f);
    }
    __syncthreads();
    float mu = mu_s, rs = rs_s;
    float4 gv = *(const float4*)(gam + t * 4);
    float4 bv = *(const float4*)(bet + t * 4);
    float ox = (v.x - mu) * rs * gv.x + bv.x;
    float oy = (v.y - mu) * rs * gv.y + bv.y;
    float oz = (v.z - mu) * rs * gv.z + bv.z;
    float ow = (v.w - mu) * rs * gv.w + bv.w;
    orow[t * 2 + 0] = __floats2half2_rn(ox, oy);
    orow[t * 2 + 1] = __floats2half2_rn(oz, ow);
}

// ---------------- fp16 mma GEMM: C = A(MxK)*B(NxK)^T (+bias)(+res), fp32 out -
// 128x128 tile, BK=32 halves, 4-stage cp.async, 256 threads, warp tile 64x32.
#define APITCH 80                      // bytes per smem row (64B data + 16B pad)
#define ATILE_B (128 * APITCH)         // 10240
#define STAGE_B (2 * ATILE_B)          // 20480
#define HSMEM_BYTES (4 * STAGE_B)      // 81920

template<bool BIAS, bool RES>
__global__ void __launch_bounds__(256, 2) hgemm(
    const __half* __restrict__ A, const __half* __restrict__ Bm,
    const float* __restrict__ bias, const float* __restrict__ res,
    float* __restrict__ Cc, int M, int Nn, int K)
{
    extern __shared__ char smc[];
    uint32_t sb = smem_u32(smc);
    const int tid = threadIdx.x;
    const int warp = tid >> 5, lane = tid & 31;
    const int m0 = blockIdx.y * 128, n0 = blockIdx.x * 128;
    const int wm = (warp >> 2) * 64, wn = (warp & 3) * 32;
    const int gr = lane >> 2, q = lane & 3;
    const int oct = lane >> 3, orow = lane & 7;

    // cp.async geometry: thread -> (row, 32B chunk-pair)
    const int lrow = tid >> 1;
    const int lc = (tid & 1) * 2;                  // chunk index (16B units): 0 or 2
    const __half* Ap = A  + (size_t)(m0 + lrow) * K + lc * 8;
    const __half* Bp = Bm + (size_t)(n0 + lrow) * K + lc * 8;
    const uint32_t woA = (uint32_t)lrow * APITCH + lc * 16;
    const uint32_t woB = woA + ATILE_B;

    float acc[4][4][4];
    #pragma unroll
    for (int i = 0; i < 4; i++)
        #pragma unroll
        for (int j = 0; j < 4; j++)
            #pragma unroll
            for (int c = 0; c < 4; c++) acc[i][j][c] = 0.f;

    const int NS = K >> 5;

    #pragma unroll
    for (int s = 0; s < 3; s++) {
        uint32_t st = sb + (uint32_t)s * STAGE_B;
        CP_ASYNC16(st + woA,      Ap + (size_t)s * 32);
        CP_ASYNC16(st + woA + 16, Ap + (size_t)s * 32 + 8);
        CP_ASYNC16(st + woB,      Bp + (size_t)s * 32);
        CP_ASYNC16(st + woB + 16, Bp + (size_t)s * 32 + 8);
        CP_COMMIT();
    }

    for (int s = 0; s < NS; s++) {
        CP_WAIT(2);
        __syncthreads();

        int ns = s + 3;
        if (ns < NS) {
            uint32_t st = sb + (uint32_t)(ns & 3) * STAGE_B;
            CP_ASYNC16(st + woA,      Ap + (size_t)ns * 32);
            CP_ASYNC16(st + woA + 16, Ap + (size_t)ns * 32 + 8);
            CP_ASYNC16(st + woB,      Bp + (size_t)ns * 32);
            CP_ASYNC16(st + woB + 16, Bp + (size_t)ns * 32 + 8);
            CP_COMMIT();
        } else {
            CP_COMMIT();   // empty group keeps CP_WAIT(2) accounting uniform
        }

        uint32_t ab = sb + (uint32_t)(s & 3) * STAGE_B;
        uint32_t bb = ab + ATILE_B;

        #pragma unroll
        for (int kk = 0; kk < 2; kk++) {
            uint32_t a[4][4], b[2][4];
            const int kc = kk * 2 + (oct >> 1);
            #pragma unroll
            for (int mi = 0; mi < 4; mi++) {
                int r = wm + mi * 16 + (oct & 1) * 8 + orow;
                LDM_X4(a[mi][0], a[mi][1], a[mi][2], a[mi][3],
                       ab + (uint32_t)r * APITCH + kc * 16);
            }
            #pragma unroll
            for (int nj = 0; nj < 2; nj++) {
                int r = wn + nj * 16 + (oct & 1) * 8 + orow;
                LDM_X4(b[nj][0], b[nj][1], b[nj][2], b[nj][3],
                       bb + (uint32_t)r * APITCH + kc * 16);
            }
            #pragma unroll
            for (int mi = 0; mi < 4; mi++) {
                #pragma unroll
                for (int nj = 0; nj < 2; nj++) {
                    mma_f16(acc[mi][nj * 2 + 0], a[mi], b[nj][0], b[nj][2]);
                    mma_f16(acc[mi][nj * 2 + 1], a[mi], b[nj][1], b[nj][3]);
                }
            }
        }
    }

    // epilogue
    #pragma unroll
    for (int mi = 0; mi < 4; mi++) {
        int m = m0 + wm + mi * 16 + gr;
        #pragma unroll
        for (int ni = 0; ni < 4; ni++) {
            int n = n0 + wn + ni * 8 + 2 * q;
            float2 v0 = make_float2(acc[mi][ni][0], acc[mi][ni][1]);
            float2 v1 = make_float2(acc[mi][ni][2], acc[mi][ni][3]);
            if (BIAS) {
                float2 bv = *(const float2*)(bias + n);
                v0.x += bv.x; v0.y += bv.y;
                v1.x += bv.x; v1.y += bv.y;
            }
            if (RES) {
                float2 r0 = *(const float2*)(res + (size_t)m * Nn + n);
                float2 r1 = *(const float2*)(res + (size_t)(m + 8) * Nn + n);
                v0.x += r0.x; v0.y += r0.y;
                v1.x += r1.x; v1.y += r1.y;
            }
            *(float2*)(Cc + (size_t)m * Nn + n) = v0;
            *(float2*)(Cc + (size_t)(m + 8) * Nn + n) = v1;
        }
    }
}

// ---------------- causal flash attention (fp32 math, half output) ------------
#define BR 64
#define BC 64

__global__ void __launch_bounds__(64) flash_attn_k(
    const float* __restrict__ qkv, __half* __restrict__ O)
{
    int qt = blockIdx.x;
    int bh = blockIdx.y;
    int b = bh / H_, h = bh % H_;
    int t = threadIdx.x;
    int qi = qt * BR + t;

    const float* base = qkv + (size_t)b * N_ * (3 * C_);
    const float* qp = base + (size_t)qi * (3 * C_) + h * D_;

    float4 q4[16];
    #pragma unroll
    for (int d = 0; d < 16; d++) {
        float4 v = *(const float4*)(qp + d * 4);
        v.x *= 0.125f; v.y *= 0.125f; v.z *= 0.125f; v.w *= 0.125f;
        q4[d] = v;
    }

    float m = -INFINITY, l = 0.f;
    float4 acc[16];
    #pragma unroll
    for (int d = 0; d < 16; d++) acc[d] = make_float4(0.f, 0.f, 0.f, 0.f);

    __shared__ float4 Ks[BC][16];
    __shared__ float4 Vs[BC][16];
    __shared__ float  Ss[BC][BR];

    int nkt = qt + 1;
    for (int kt = 0; kt < nkt; kt++) {
        __syncthreads();
        for (int j = 0; j < BC; j++) {
            const float* kp = base + (size_t)(kt * BC + j) * (3 * C_) + C_ + h * D_;
            ((float*)&Ks[j][0])[t] = kp[t];
            ((float*)&Vs[j][0])[t] = kp[C_ + t];
        }
        __syncthreads();

        int jmax = (kt == qt) ? (t + 1) : BC;
        float mt = -INFINITY;
        for (int j = 0; j < jmax; j++) {
            float s = 0.f;
            #pragma unroll
            for (int d = 0; d < 16; d++) {
                float4 kv = Ks[j][d];
                s = fmaf(q4[d].x, kv.x, s);
                s = fmaf(q4[d].y, kv.y, s);
                s = fmaf(q4[d].z, kv.z, s);
                s = fmaf(q4[d].w, kv.w, s);
            }
            Ss[j][t] = s;
            mt = fmaxf(mt, s);
        }
        float nm = fmaxf(m, mt);
        float corr = __expf(m - nm);
        l *= corr;
        #pragma unroll
        for (int d = 0; d < 16; d++) {
            acc[d].x *= corr; acc[d].y *= corr; acc[d].z *= corr; acc[d].w *= corr;
        }
        for (int j = 0; j < jmax; j++) {
            float p = __expf(Ss[j][t] - nm);
            l += p;
            #pragma unroll
            for (int d = 0; d < 16; d++) {
                float4 vv = Vs[j][d];
                acc[d].x = fmaf(p, vv.x, acc[d].x);
                acc[d].y = fmaf(p, vv.y, acc[d].y);
                acc[d].z = fmaf(p, vv.z, acc[d].z);
                acc[d].w = fmaf(p, vv.w, acc[d].w);
            }
        }
        m = nm;
    }

    float inv = 1.f / l;
    __half2* op = (__half2*)(O + (size_t)b * N_ * C_ + (size_t)qi * C_ + h * D_);
    #pragma unroll
    for (int d = 0; d < 16; d++) {
        op[d * 2 + 0] = __floats2half2_rn(acc[d].x * inv, acc[d].y * inv);
        op[d * 2 + 1] = __floats2half2_rn(acc[d].z * inv, acc[d].w * inv);
    }
}

// ---------------- silu(u) * g -> half ----------------------------------------
__global__ void __launch_bounds__(256) silu_mul_k(
    const float* __restrict__ u, const float* __restrict__ g,
    __half* __restrict__ out, int n4)
{
    int i = blockIdx.x * 256 + threadIdx.x;
    if (i < n4) {
        float4 a = ((const float4*)u)[i];
        float4 b = ((const float4*)g)[i];
        float ox = a.x / (1.f + __expf(-a.x)) * b.x;
        float oy = a.y / (1.f + __expf(-a.y)) * b.y;
        float oz = a.z / (1.f + __expf(-a.z)) * b.z;
        float ow = a.w / (1.f + __expf(-a.w)) * b.w;
        __half2* o = (__half2*)out + i * 2;
        o[0] = __floats2half2_rn(ox, oy);
        o[1] = __floats2half2_rn(oz, ow);
    }
}

// ---------------- launcher ---------------------------------------------------
extern "C" void kernel_launch(void* const* d_in, const int* in_sizes, int n_in,
                              void* d_out, int out_size)
{
    const float* x      = (const float*)d_in[0];
    const float* qkv_w  = (const float*)d_in[2];
    const float* qkv_b  = (const float*)d_in[3];
    const float* proj_w = (const float*)d_in[4];
    const float* proj_b = (const float*)d_in[5];
    const float* ln1_g  = (const float*)d_in[6];
    const float* ln1_b  = (const float*)d_in[7];
    const float* ln2_g  = (const float*)d_in[8];
    const float* ln2_b  = (const float*)d_in[9];
    const float* w1     = (const float*)d_in[10];
    const float* w2     = (const float*)d_in[11];
    const float* w3     = (const float*)d_in[12];
    float* out = (float*)d_out;

    float *qkv, *x1, *u, *g;
    __half *hh, *oh, *uh, *wq, *wp, *tw1, *tw2, *tw3;
    cudaGetSymbolAddress((void**)&qkv, g_qkv);
    cudaGetSymbolAddress((void**)&x1,  g_x1);
    cudaGetSymbolAddress((void**)&u,   g_u);
    cudaGetSymbolAddress((void**)&g,   g_g);
    cudaGetSymbolAddress((void**)&hh,  g_hh);
    cudaGetSymbolAddress((void**)&oh,  g_oh);
    cudaGetSymbolAddress((void**)&uh,  g_uh);
    cudaGetSymbolAddress((void**)&wq,  g_wqh);
    cudaGetSymbolAddress((void**)&wp,  g_wph);
    cudaGetSymbolAddress((void**)&tw1, g_w1h);
    cudaGetSymbolAddress((void**)&tw2, g_w2h);
    cudaGetSymbolAddress((void**)&tw3, g_w3h);

    cudaFuncSetAttribute(hgemm<true,  false>, cudaFuncAttributeMaxDynamicSharedMemorySize, HSMEM_BYTES);
    cudaFuncSetAttribute(hgemm<true,  true >, cudaFuncAttributeMaxDynamicSharedMemorySize, HSMEM_BYTES);
    cudaFuncSetAttribute(hgemm<false, false>, cudaFuncAttributeMaxDynamicSharedMemorySize, HSMEM_BYTES);
    cudaFuncSetAttribute(hgemm<false, true >, cudaFuncAttributeMaxDynamicSharedMemorySize, HSMEM_BYTES);

    // 0) weights -> fp16 (rn)
    cvt_half_k<<<(3*C_*C_/4 + 255)/256, 256>>>(qkv_w,  wq,  3*C_*C_/4);
    cvt_half_k<<<(C_*C_/4   + 255)/256, 256>>>(proj_w, wp,  C_*C_/4);
    cvt_half_k<<<(FF_*C_/4  + 255)/256, 256>>>(w1,     tw1, FF_*C_/4);
    cvt_half_k<<<(C_*FF_/4  + 255)/256, 256>>>(w2,     tw2, C_*FF_/4);
    cvt_half_k<<<(FF_*C_/4  + 255)/256, 256>>>(w3,     tw3, FF_*C_/4);

    // 1) hh = LN1(x)  (half)
    layernorm_k<<<M_, 256>>>(x, ln1_g, ln1_b, hh);
    // 2) qkv = hh @ qkv_w^T + qkv_b  (fp32 out)
    hgemm<true, false><<<dim3(3*C_/128, M_/128), 256, HSMEM_BYTES>>>(
        hh, wq, qkv_b, nullptr, qkv, M_, 3*C_, C_);
    // 3) oh = causal_attention(qkv)  (half out)
    flash_attn_k<<<dim3(N_/BR, B_*H_), 64>>>(qkv, oh);
    // 4) x1 = x + oh @ proj_w^T + proj_b
    hgemm<true, true><<<dim3(C_/128, M_/128), 256, HSMEM_BYTES>>>(
        oh, wp, proj_b, x, x1, M_, C_, C_);
    // 5) hh = LN2(x1)
    layernorm_k<<<M_, 256>>>(x1, ln2_g, ln2_b, hh);
    // 6) u = hh @ w1^T ; g = hh @ w3^T
    hgemm<false, false><<<dim3(FF_/128, M_/128), 256, HSMEM_BYTES>>>(
        hh, tw1, nullptr, nullptr, u, M_, FF_, C_);
    hgemm<false, false><<<dim3(FF_/128, M_/128), 256, HSMEM_BYTES>>>(
        hh, tw3, nullptr, nullptr, g, M_, FF_, C_);
    // 7) uh = silu(u) * g  (half)
    silu_mul_k<<<(M_*FF_/4)/256, 256>>>(u, g, uh, M_*FF_/4);
    // 8) out = x1 + uh @ w2^T
    hgemm<false, true><<<dim3(C_/128, M_/128), 256, HSMEM_BYTES>>>(
        uh, tw2, nullptr, x1, out, M_, C_, FF_);
}

// round 12
// speedup vs baseline: 6.1690x; 2.0132x over previous
#include <cuda_runtime.h>
#include <cuda_fp16.h>
#include <math.h>
#include <stdint.h>

#define B_ 4
#define N_ 2048
#define C_ 1024
#define H_ 16
#define D_ 64
#define FF_ 4096
#define M_ (B_ * N_)   // 8192 rows

// ---------------- scratch ----------------------------------------------------
__device__ float  g_x1 [M_ * C_];      // residual after attention (fp32)
__device__ __half g_hh [M_ * C_];      // LN output (half)
__device__ __half g_qkvh[M_ * 3 * C_]; // qkv projections (half)
__device__ __half g_oh [M_ * C_];      // attention output (half)
__device__ __half g_ah [M_ * FF_];     // h@w1^T  -> silu(a)*b (half)
__device__ __half g_bh [M_ * FF_];     // h@w3^T (half)
// fp16 weights
__device__ __half g_wqh[3 * C_ * C_];
__device__ __half g_wph[C_ * C_];
__device__ __half g_w1h[FF_ * C_];
__device__ __half g_w2h[C_ * FF_];
__device__ __half g_w3h[FF_ * C_];

// ---------------- helpers ----------------------------------------------------
__device__ __forceinline__ uint32_t smem_u32(const void* p) {
    uint32_t a;
    asm("{ .reg .u64 t; cvta.to.shared.u64 t, %1; cvt.u32.u64 %0, t; }" : "=r"(a) : "l"(p));
    return a;
}
__device__ __forceinline__ uint32_t h2_u32(__half2 h) {
    return *reinterpret_cast<uint32_t*>(&h);
}
__device__ __forceinline__ __half2 u32_h2(uint32_t u) {
    return *reinterpret_cast<__half2*>(&u);
}
#define CP_ASYNC16(dst, src) \
    asm volatile("cp.async.cg.shared.global [%0], [%1], 16;" :: "r"(dst), "l"(src))
#define CP_COMMIT() asm volatile("cp.async.commit_group;" ::: "memory")
#define CP_WAIT(n)  asm volatile("cp.async.wait_group %0;" :: "n"(n) : "memory")

#define LDM_X4(r0, r1, r2, r3, addr) \
    asm volatile("ldmatrix.sync.aligned.m8n8.x4.shared.b16 {%0,%1,%2,%3}, [%4];" \
                 : "=r"(r0), "=r"(r1), "=r"(r2), "=r"(r3) : "r"(addr))
#define LDM_X4_T(r0, r1, r2, r3, addr) \
    asm volatile("ldmatrix.sync.aligned.m8n8.x4.trans.shared.b16 {%0,%1,%2,%3}, [%4];" \
                 : "=r"(r0), "=r"(r1), "=r"(r2), "=r"(r3) : "r"(addr))

__device__ __forceinline__ void mma_f16(float* c, const uint32_t* a,
                                        uint32_t b0, uint32_t b1) {
    asm volatile(
        "mma.sync.aligned.m16n8k16.row.col.f32.f16.f16.f32 "
        "{%0,%1,%2,%3}, {%4,%5,%6,%7}, {%8,%9}, {%0,%1,%2,%3};"
        : "+f"(c[0]), "+f"(c[1]), "+f"(c[2]), "+f"(c[3])
        : "r"(a[0]), "r"(a[1]), "r"(a[2]), "r"(a[3]), "r"(b0), "r"(b1));
}

// ---------------- fp32 -> fp16 prepass ---------------------------------------
__global__ void __launch_bounds__(256) cvt_half_k(const float* __restrict__ in,
                                                  __half* __restrict__ out, int n4)
{
    int i = blockIdx.x * 256 + threadIdx.x;
    if (i < n4) {
        float4 v = ((const float4*)in)[i];
        __half2* o = (__half2*)out + i * 2;
        o[0] = __floats2half2_rn(v.x, v.y);
        o[1] = __floats2half2_rn(v.z, v.w);
    }
}

// ---------------- LayerNorm (half output) ------------------------------------
__global__ void __launch_bounds__(256) layernorm_k(
    const float* __restrict__ x, const float* __restrict__ gam,
    const float* __restrict__ bet, __half* __restrict__ out)
{
    int row = blockIdx.x;
    const float* xr = x + (size_t)row * C_;
    __half2* orow = (__half2*)(out + (size_t)row * C_);
    int t = threadIdx.x;

    float4 v = *(const float4*)(xr + t * 4);
    float s1 = v.x + v.y + v.z + v.w;
    float s2 = v.x*v.x + v.y*v.y + v.z*v.z + v.w*v.w;
    #pragma unroll
    for (int o = 16; o; o >>= 1) {
        s1 += __shfl_xor_sync(0xffffffffu, s1, o);
        s2 += __shfl_xor_sync(0xffffffffu, s2, o);
    }
    __shared__ float r1[8], r2[8];
    __shared__ float mu_s, rs_s;
    if ((t & 31) == 0) { r1[t >> 5] = s1; r2[t >> 5] = s2; }
    __syncthreads();
    if (t == 0) {
        float a = 0.f, b = 0.f;
        #pragma unroll
        for (int i = 0; i < 8; i++) { a += r1[i]; b += r2[i]; }
        float mu = a * (1.f / C_);
        float var = b * (1.f / C_) - mu * mu;
        mu_s = mu; rs_s = rsqrtf(var + 1e-6f);
    }
    __syncthreads();
    float mu = mu_s, rs = rs_s;
    float4 gv = *(const float4*)(gam + t * 4);
    float4 bv = *(const float4*)(bet + t * 4);
    float ox = (v.x - mu) * rs * gv.x + bv.x;
    float oy = (v.y - mu) * rs * gv.y + bv.y;
    float oz = (v.z - mu) * rs * gv.z + bv.z;
    float ow = (v.w - mu) * rs * gv.w + bv.w;
    orow[t * 2 + 0] = __floats2half2_rn(ox, oy);
    orow[t * 2 + 1] = __floats2half2_rn(oz, ow);
}

// ---------------- fp16 mma GEMM: C = A(MxK)*B(NxK)^T (+bias)(+res) -----------
// 128x128 tile, BK=32 halves, 4-stage cp.async, 256 threads, warp tile 64x32.
#define APITCH 80                      // bytes per smem row (64B data + 16B pad)
#define ATILE_B (128 * APITCH)         // 10240
#define STAGE_B (2 * ATILE_B)          // 20480
#define HSMEM_BYTES (4 * STAGE_B)      // 81920

template<bool BIAS, bool RES, bool HOUT>
__global__ void __launch_bounds__(256, 2) hgemm(
    const __half* __restrict__ A, const __half* __restrict__ Bm,
    const float* __restrict__ bias, const float* __restrict__ res,
    void* __restrict__ Cc, int M, int Nn, int K)
{
    extern __shared__ char smc[];
    uint32_t sb = smem_u32(smc);
    const int tid = threadIdx.x;
    const int warp = tid >> 5, lane = tid & 31;
    const int m0 = blockIdx.y * 128, n0 = blockIdx.x * 128;
    const int wm = (warp >> 2) * 64, wn = (warp & 3) * 32;
    const int gr = lane >> 2, q = lane & 3;
    const int oct = lane >> 3, orow = lane & 7;

    const int lrow = tid >> 1;
    const int lc = (tid & 1) * 2;
    const __half* Ap = A  + (size_t)(m0 + lrow) * K + lc * 8;
    const __half* Bp = Bm + (size_t)(n0 + lrow) * K + lc * 8;
    const uint32_t woA = (uint32_t)lrow * APITCH + lc * 16;
    const uint32_t woB = woA + ATILE_B;

    float acc[4][4][4];
    #pragma unroll
    for (int i = 0; i < 4; i++)
        #pragma unroll
        for (int j = 0; j < 4; j++)
            #pragma unroll
            for (int c = 0; c < 4; c++) acc[i][j][c] = 0.f;

    const int NS = K >> 5;

    #pragma unroll
    for (int s = 0; s < 3; s++) {
        uint32_t st = sb + (uint32_t)s * STAGE_B;
        CP_ASYNC16(st + woA,      Ap + (size_t)s * 32);
        CP_ASYNC16(st + woA + 16, Ap + (size_t)s * 32 + 8);
        CP_ASYNC16(st + woB,      Bp + (size_t)s * 32);
        CP_ASYNC16(st + woB + 16, Bp + (size_t)s * 32 + 8);
        CP_COMMIT();
    }

    for (int s = 0; s < NS; s++) {
        CP_WAIT(2);
        __syncthreads();

        int ns = s + 3;
        if (ns < NS) {
            uint32_t st = sb + (uint32_t)(ns & 3) * STAGE_B;
            CP_ASYNC16(st + woA,      Ap + (size_t)ns * 32);
            CP_ASYNC16(st + woA + 16, Ap + (size_t)ns * 32 + 8);
            CP_ASYNC16(st + woB,      Bp + (size_t)ns * 32);
            CP_ASYNC16(st + woB + 16, Bp + (size_t)ns * 32 + 8);
            CP_COMMIT();
        } else {
            CP_COMMIT();
        }

        uint32_t ab = sb + (uint32_t)(s & 3) * STAGE_B;
        uint32_t bb = ab + ATILE_B;

        #pragma unroll
        for (int kk = 0; kk < 2; kk++) {
            uint32_t a[4][4], b[2][4];
            const int kc = kk * 2 + (oct >> 1);
            #pragma unroll
            for (int mi = 0; mi < 4; mi++) {
                int r = wm + mi * 16 + (oct & 1) * 8 + orow;
                LDM_X4(a[mi][0], a[mi][1], a[mi][2], a[mi][3],
                       ab + (uint32_t)r * APITCH + kc * 16);
            }
            #pragma unroll
            for (int nj = 0; nj < 2; nj++) {
                int r = wn + nj * 16 + (oct & 1) * 8 + orow;
                LDM_X4(b[nj][0], b[nj][1], b[nj][2], b[nj][3],
                       bb + (uint32_t)r * APITCH + kc * 16);
            }
            #pragma unroll
            for (int mi = 0; mi < 4; mi++) {
                #pragma unroll
                for (int nj = 0; nj < 2; nj++) {
                    mma_f16(acc[mi][nj * 2 + 0], a[mi], b[nj][0], b[nj][2]);
                    mma_f16(acc[mi][nj * 2 + 1], a[mi], b[nj][1], b[nj][3]);
                }
            }
        }
    }

    #pragma unroll
    for (int mi = 0; mi < 4; mi++) {
        int m = m0 + wm + mi * 16 + gr;
        #pragma unroll
        for (int ni = 0; ni < 4; ni++) {
            int n = n0 + wn + ni * 8 + 2 * q;
            float2 v0 = make_float2(acc[mi][ni][0], acc[mi][ni][1]);
            float2 v1 = make_float2(acc[mi][ni][2], acc[mi][ni][3]);
            if (BIAS) {
                float2 bv = *(const float2*)(bias + n);
                v0.x += bv.x; v0.y += bv.y;
                v1.x += bv.x; v1.y += bv.y;
            }
            if (RES) {
                float2 r0 = *(const float2*)(res + (size_t)m * Nn + n);
                float2 r1 = *(const float2*)(res + (size_t)(m + 8) * Nn + n);
                v0.x += r0.x; v0.y += r0.y;
                v1.x += r1.x; v1.y += r1.y;
            }
            if (HOUT) {
                __half* Ch = (__half*)Cc;
                *(__half2*)(Ch + (size_t)m * Nn + n)       = __floats2half2_rn(v0.x, v0.y);
                *(__half2*)(Ch + (size_t)(m + 8) * Nn + n) = __floats2half2_rn(v1.x, v1.y);
            } else {
                float* Cf = (float*)Cc;
                *(float2*)(Cf + (size_t)m * Nn + n) = v0;
                *(float2*)(Cf + (size_t)(m + 8) * Nn + n) = v1;
            }
        }
    }
}

// ---------------- tensor-core causal flash attention --------------------------
// BR=128 (8 warps x 16 rows), BC=64. fp16 mma, fp32 softmax/accum.
#define FA_BR 128
#define FA_BC 64
#define FA_PITCH 72                    // halves per smem row (144B)

__global__ void __launch_bounds__(256, 2) flash16_k(
    const __half* __restrict__ qkv, __half* __restrict__ O)
{
    __shared__ __half Qs[FA_BR * FA_PITCH];
    __shared__ __half Ks[FA_BC * FA_PITCH];
    __shared__ __half Vs[FA_BC * FA_PITCH];

    const int qt = (int)gridDim.x - 1 - (int)blockIdx.x;   // heavy tiles first
    const int bh = blockIdx.y;
    const int b = bh >> 4, h = bh & 15;
    const int tid = threadIdx.x, warp = tid >> 5, lane = tid & 31;
    const int gr = lane >> 2, q = lane & 3;
    const int wq = warp * 16;
    const int qr0 = qt * FA_BR;

    const uint32_t qb = smem_u32(Qs);
    const uint32_t kb = smem_u32(Ks);
    const uint32_t vb = smem_u32(Vs);

    const size_t rstride = 3 * C_;
    const __half* qbase = qkv + (size_t)(b * N_) * rstride + h * D_;

    // load Q tile (128 rows x 64 halves)
    #pragma unroll
    for (int i = 0; i < 4; i++) {
        int idx = tid + i * 256;
        int r = idx >> 3, c = idx & 7;
        *(uint4*)(Qs + r * FA_PITCH + c * 8) =
            *(const uint4*)(qbase + (size_t)(qr0 + r) * rstride + c * 8);
    }
    __syncthreads();

    // preload Q A-fragments (whole 16x64 warp slab)
    uint32_t qa[4][4];
    {
        int r = wq + (lane & 15);
        #pragma unroll
        for (int kc = 0; kc < 4; kc++) {
            int ch = kc * 2 + (lane >> 4);
            LDM_X4(qa[kc][0], qa[kc][1], qa[kc][2], qa[kc][3],
                   qb + (uint32_t)(r * FA_PITCH + ch * 8) * 2);
        }
    }

    float m0 = -INFINITY, m1 = -INFINITY, l0 = 0.f, l1 = 0.f;
    float o[8][4];
    #pragma unroll
    for (int i = 0; i < 8; i++)
        #pragma unroll
        for (int j = 0; j < 4; j++) o[i][j] = 0.f;

    const int row0 = qr0 + wq + gr;
    const int row1 = row0 + 8;
    const int nkt = 2 * qt + 2;

    for (int kt = 0; kt < nkt; kt++) {
        __syncthreads();
        const __half* kbase = qkv + (size_t)(b * N_ + kt * FA_BC) * rstride + C_ + h * D_;
        #pragma unroll
        for (int i = 0; i < 2; i++) {
            int idx = tid + i * 256;
            int r = idx >> 3, c = idx & 7;
            *(uint4*)(Ks + r * FA_PITCH + c * 8) =
                *(const uint4*)(kbase + (size_t)r * rstride + c * 8);
            *(uint4*)(Vs + r * FA_PITCH + c * 8) =
                *(const uint4*)(kbase + (size_t)r * rstride + C_ + c * 8);
        }
        __syncthreads();

        // S = Q @ K^T  (16 x 64 per warp)
        float sc[8][4];
        #pragma unroll
        for (int i = 0; i < 8; i++)
            #pragma unroll
            for (int j = 0; j < 4; j++) sc[i][j] = 0.f;

        {
            int rk = (lane & 15);
            #pragma unroll
            for (int kc = 0; kc < 4; kc++) {
                int ch = kc * 2 + (lane >> 4);
                #pragma unroll
                for (int nj = 0; nj < 4; nj++) {
                    uint32_t b0, b1, b2, b3;
                    LDM_X4(b0, b1, b2, b3,
                           kb + (uint32_t)((nj * 16 + rk) * FA_PITCH + ch * 8) * 2);
                    mma_f16(sc[nj * 2 + 0], qa[kc], b0, b2);
                    mma_f16(sc[nj * 2 + 1], qa[kc], b1, b3);
                }
            }
        }

        // scale + causal mask + row max
        const bool need_mask = (kt * FA_BC + FA_BC - 1) > (qr0 + wq);
        float mt0 = -INFINITY, mt1 = -INFINITY;
        #pragma unroll
        for (int nt = 0; nt < 8; nt++) {
            int key = kt * FA_BC + nt * 8 + 2 * q;
            #pragma unroll
            for (int j = 0; j < 4; j++) {
                float s = sc[nt][j] * 0.125f;
                if (need_mask) {
                    int k_ = key + (j & 1);
                    int r_ = (j < 2) ? row0 : row1;
                    if (k_ > r_) s = -INFINITY;
                }
                sc[nt][j] = s;
            }
            mt0 = fmaxf(mt0, fmaxf(sc[nt][0], sc[nt][1]));
            mt1 = fmaxf(mt1, fmaxf(sc[nt][2], sc[nt][3]));
        }
        mt0 = fmaxf(mt0, __shfl_xor_sync(0xffffffffu, mt0, 1));
        mt0 = fmaxf(mt0, __shfl_xor_sync(0xffffffffu, mt0, 2));
        mt1 = fmaxf(mt1, __shfl_xor_sync(0xffffffffu, mt1, 1));
        mt1 = fmaxf(mt1, __shfl_xor_sync(0xffffffffu, mt1, 2));

        float nm0 = fmaxf(m0, mt0), nm1 = fmaxf(m1, mt1);
        float corr0 = __expf(m0 - nm0), corr1 = __expf(m1 - nm1);
        m0 = nm0; m1 = nm1;
        #pragma unroll
        for (int nt = 0; nt < 8; nt++) {
            o[nt][0] *= corr0; o[nt][1] *= corr0;
            o[nt][2] *= corr1; o[nt][3] *= corr1;
        }
        l0 *= corr0; l1 *= corr1;

        // per-16-key group: exponentiate, pack P, P @ V
        #pragma unroll
        for (int kg = 0; kg < 4; kg++) {
            float p00 = __expf(sc[2*kg][0]   - nm0), p01 = __expf(sc[2*kg][1]   - nm0);
            float p10 = __expf(sc[2*kg][2]   - nm1), p11 = __expf(sc[2*kg][3]   - nm1);
            float p20 = __expf(sc[2*kg+1][0] - nm0), p21 = __expf(sc[2*kg+1][1] - nm0);
            float p30 = __expf(sc[2*kg+1][2] - nm1), p31 = __expf(sc[2*kg+1][3] - nm1);
            l0 += p00 + p01 + p20 + p21;
            l1 += p10 + p11 + p30 + p31;
            uint32_t P[4];
            P[0] = h2_u32(__floats2half2_rn(p00, p01));
            P[1] = h2_u32(__floats2half2_rn(p10, p11));
            P[2] = h2_u32(__floats2half2_rn(p20, p21));
            P[3] = h2_u32(__floats2half2_rn(p30, p31));
            int rv = kg * 16 + (lane & 15);
            #pragma unroll
            for (int dj = 0; dj < 4; dj++) {
                uint32_t v0, v1, v2, v3;
                LDM_X4_T(v0, v1, v2, v3,
                         vb + (uint32_t)(rv * FA_PITCH + (dj * 2 + (lane >> 4)) * 8) * 2);
                mma_f16(o[dj * 2 + 0], P, v0, v1);
                mma_f16(o[dj * 2 + 1], P, v2, v3);
            }
        }
    }

    // FIX: l is a row quantity — sum partial l across the quad (lanes differing
    // in q hold disjoint key subsets of the same row). Without this, threads
    // whose private keys are all causally masked have l=0 -> inv=INF -> NaN.
    l0 += __shfl_xor_sync(0xffffffffu, l0, 1);
    l0 += __shfl_xor_sync(0xffffffffu, l0, 2);
    l1 += __shfl_xor_sync(0xffffffffu, l1, 1);
    l1 += __shfl_xor_sync(0xffffffffu, l1, 2);

    float inv0 = 1.f / l0, inv1 = 1.f / l1;
    __half* ob = O + (size_t)(b * N_) * C_ + h * D_;
    #pragma unroll
    for (int nt = 0; nt < 8; nt++) {
        int d = nt * 8 + 2 * q;
        *(__half2*)(ob + (size_t)row0 * C_ + d) =
            __floats2half2_rn(o[nt][0] * inv0, o[nt][1] * inv0);
        *(__half2*)(ob + (size_t)row1 * C_ + d) =
            __floats2half2_rn(o[nt][2] * inv1, o[nt][3] * inv1);
    }
}

// ---------------- silu(a) * b (half in/out) ----------------------------------
__global__ void __launch_bounds__(256) silu_mul_k(
    const __half* __restrict__ a, const __half* __restrict__ bb,
    __half* __restrict__ out, int n8)
{
    int i = blockIdx.x * 256 + threadIdx.x;
    if (i < n8) {
        uint4 av = ((const uint4*)a)[i];
        uint4 bv = ((const uint4*)bb)[i];
        uint32_t* ap = (uint32_t*)&av;
        uint32_t* bp = (uint32_t*)&bv;
        uint4 ov;
        uint32_t* op = (uint32_t*)&ov;
        #pragma unroll
        for (int j = 0; j < 4; j++) {
            float2 af = __half22float2(u32_h2(ap[j]));
            float2 bf = __half22float2(u32_h2(bp[j]));
            float ox = af.x / (1.f + __expf(-af.x)) * bf.x;
            float oy = af.y / (1.f + __expf(-af.y)) * bf.y;
            op[j] = h2_u32(__floats2half2_rn(ox, oy));
        }
        ((uint4*)out)[i] = ov;
    }
}

// ---------------- launcher ---------------------------------------------------
extern "C" void kernel_launch(void* const* d_in, const int* in_sizes, int n_in,
                              void* d_out, int out_size)
{
    const float* x      = (const float*)d_in[0];
    const float* qkv_w  = (const float*)d_in[2];
    const float* qkv_b  = (const float*)d_in[3];
    const float* proj_w = (const float*)d_in[4];
    const float* proj_b = (const float*)d_in[5];
    const float* ln1_g  = (const float*)d_in[6];
    const float* ln1_b  = (const float*)d_in[7];
    const float* ln2_g  = (const float*)d_in[8];
    const float* ln2_b  = (const float*)d_in[9];
    const float* w1     = (const float*)d_in[10];
    const float* w2     = (const float*)d_in[11];
    const float* w3     = (const float*)d_in[12];
    float* out = (float*)d_out;

    float *x1;
    __half *hh, *qkvh, *oh, *ah, *bh, *wq, *wp, *tw1, *tw2, *tw3;
    cudaGetSymbolAddress((void**)&x1,   g_x1);
    cudaGetSymbolAddress((void**)&hh,   g_hh);
    cudaGetSymbolAddress((void**)&qkvh, g_qkvh);
    cudaGetSymbolAddress((void**)&oh,   g_oh);
    cudaGetSymbolAddress((void**)&ah,   g_ah);
    cudaGetSymbolAddress((void**)&bh,   g_bh);
    cudaGetSymbolAddress((void**)&wq,   g_wqh);
    cudaGetSymbolAddress((void**)&wp,   g_wph);
    cudaGetSymbolAddress((void**)&tw1,  g_w1h);
    cudaGetSymbolAddress((void**)&tw2,  g_w2h);
    cudaGetSymbolAddress((void**)&tw3,  g_w3h);

    cudaFuncSetAttribute(hgemm<true,  false, true >, cudaFuncAttributeMaxDynamicSharedMemorySize, HSMEM_BYTES);
    cudaFuncSetAttribute(hgemm<true,  true,  false>, cudaFuncAttributeMaxDynamicSharedMemorySize, HSMEM_BYTES);
    cudaFuncSetAttribute(hgemm<false, false, true >, cudaFuncAttributeMaxDynamicSharedMemorySize, HSMEM_BYTES);
    cudaFuncSetAttribute(hgemm<false, true,  false>, cudaFuncAttributeMaxDynamicSharedMemorySize, HSMEM_BYTES);

    // 0) weights -> fp16 (rn)
    cvt_half_k<<<(3*C_*C_/4 + 255)/256, 256>>>(qkv_w,  wq,  3*C_*C_/4);
    cvt_half_k<<<(C_*C_/4   + 255)/256, 256>>>(proj_w, wp,  C_*C_/4);
    cvt_half_k<<<(FF_*C_/4  + 255)/256, 256>>>(w1,     tw1, FF_*C_/4);
    cvt_half_k<<<(C_*FF_/4  + 255)/256, 256>>>(w2,     tw2, C_*FF_/4);
    cvt_half_k<<<(FF_*C_/4  + 255)/256, 256>>>(w3,     tw3, FF_*C_/4);

    // 1) hh = LN1(x)
    layernorm_k<<<M_, 256>>>(x, ln1_g, ln1_b, hh);
    // 2) qkvh = hh @ qkv_w^T + qkv_b  (half out)
    hgemm<true, false, true><<<dim3(3*C_/128, M_/128), 256, HSMEM_BYTES>>>(
        hh, wq, qkv_b, nullptr, qkvh, M_, 3*C_, C_);
    // 3) oh = causal_attention(qkvh)  (tensor-core flash attention)
    flash16_k<<<dim3(N_/FA_BR, B_*H_), 256>>>(qkvh, oh);
    // 4) x1 = x + oh @ proj_w^T + proj_b  (fp32 out)
    hgemm<true, true, false><<<dim3(C_/128, M_/128), 256, HSMEM_BYTES>>>(
        oh, wp, proj_b, x, x1, M_, C_, C_);
    // 5) hh = LN2(x1)
    layernorm_k<<<M_, 256>>>(x1, ln2_g, ln2_b, hh);
    // 6) ah = hh @ w1^T ; bh = hh @ w3^T  (half out)
    hgemm<false, false, true><<<dim3(FF_/128, M_/128), 256, HSMEM_BYTES>>>(
        hh, tw1, nullptr, nullptr, ah, M_, FF_, C_);
    hgemm<false, false, true><<<dim3(FF_/128, M_/128), 256, HSMEM_BYTES>>>(
        hh, tw3, nullptr, nullptr, bh, M_, FF_, C_);
    // 7) ah = silu(ah) * bh
    silu_mul_k<<<(M_*FF_/8 + 255)/256, 256>>>(ah, bh, ah, M_*FF_/8);
    // 8) out = x1 + ah @ w2^T  (fp32 out)
    hgemm<false, true, false><<<dim3(C_/128, M_/128), 256, HSMEM_BYTES>>>(
        ah, tw2, nullptr, x1, out, M_, C_, FF_);
}